// round 8
// baseline (speedup 1.0000x reference)
#include <cuda_runtime.h>
#include <cuda_bf16.h>
#include <cstdint>

// ============================================================================
// VQMetaBaseline via mma.sync bf16 (compute_103-safe):
// z_e = X @ W + b with truncation-based bf16 hi/lo split (hi = exact high 16
// bits, lo = exact residual rounded to bf16), 3 exact-product passes
// (hi*hi + hi*lo + lo*hi) as grid-z phases, fp32 accumulate ->
// argmin-index parity with fp32 reference. Then nearest/proto/logits.
// ============================================================================

#define IN_DIM 49152
#define NDIM   512
#define NK     512
#define MROWS  400
#define MPAD   512
#define NSHOT  100

// GEMM tiling (R3-proven per-CTA config)
#define BM 128
#define BN 128
#define BK 32
#define STAGES 4
#define STG_BYTES 16384            // A 8KB + B 8KB per stage
#define SMEM_GEMM (STAGES * STG_BYTES)   // 64 KB -> 3 CTAs/SM

// split-K: 3 phases (hihi, hilo, lohi) x 9 sub-splits = 27
#define SUBSPLITS 9
#define TOTSPLITS 27
#define KT_PHASE  (IN_DIM / BK)          // 512 k-tiles per phase
#define KTS_BASE  (KT_PHASE / SUBSPLITS) // 56
#define KTS_REM   (KT_PHASE % SUBSPLITS) // 8

// conv_all work partition
#define A_BLOCKS ((int)((size_t)MPAD * IN_DIM / (256 * 16)))  // 6144
#define B_KT     (IN_DIM / 64)                                // 768
#define B_BLOCKS (B_KT * (NDIM / 64))                         // 6144

// ---- scratch (static device globals; no runtime allocation) ----------------
__device__ __align__(128) __nv_bfloat16 gAhi[(size_t)MPAD * IN_DIM];
__device__ __align__(128) __nv_bfloat16 gAlo[(size_t)MPAD * IN_DIM];
__device__ __align__(128) __nv_bfloat16 gBhi[(size_t)NDIM * IN_DIM];
__device__ __align__(128) __nv_bfloat16 gBlo[(size_t)NDIM * IN_DIM];
__device__ float g_part[(size_t)TOTSPLITS * MPAD * NDIM];
__device__ float g_ze[MROWS * NDIM];
__device__ int   g_idx[MROWS];
__device__ float g_proto[20 * NDIM];

// ---- helpers ----------------------------------------------------------------
__device__ __forceinline__ uint32_t smem_u32(const void* p) {
    uint32_t a;
    asm("{ .reg .u64 t; cvta.to.shared.u64 t, %1; cvt.u32.u64 %0, t; }"
        : "=r"(a) : "l"(p));
    return a;
}
__device__ __forceinline__ void cp16(uint32_t dst, const void* src) {
    asm volatile("cp.async.cg.shared.global [%0], [%1], 16;"
                 :: "r"(dst), "l"(src) : "memory");
}
#define CP_COMMIT() asm volatile("cp.async.commit_group;" ::: "memory")
#define CP_WAIT2()  asm volatile("cp.async.wait_group 2;" ::: "memory")

__device__ __forceinline__ void ldsm4(uint32_t& r0, uint32_t& r1,
                                      uint32_t& r2, uint32_t& r3, uint32_t a) {
    asm volatile("ldmatrix.sync.aligned.m8n8.x4.shared.b16 {%0,%1,%2,%3}, [%4];"
                 : "=r"(r0), "=r"(r1), "=r"(r2), "=r"(r3) : "r"(a));
}
__device__ __forceinline__ void mma16816(float* c, const uint32_t* a,
                                         const uint32_t* b) {
    asm volatile(
        "mma.sync.aligned.m16n8k16.row.col.f32.bf16.bf16.f32 "
        "{%0,%1,%2,%3},{%4,%5,%6,%7},{%8,%9},{%0,%1,%2,%3};"
        : "+f"(c[0]), "+f"(c[1]), "+f"(c[2]), "+f"(c[3])
        : "r"(a[0]), "r"(a[1]), "r"(a[2]), "r"(a[3]), "r"(b[0]), "r"(b[1]));
}

// smem tile offset: 128 rows x 64B (32 bf16), XOR swizzle -> conflict-free
__device__ __forceinline__ uint32_t toff(int r, int c) {
    return (uint32_t)(r * 64 + ((c ^ ((r >> 1) & 3)) << 4));
}

// ---- fast truncation split: 2 floats -> 1 u32 hi-pair + 1 u32 lo-pair ------
// hi = exact top-16-bits bf16 (PRMT), lo = (x - hi) exactly in fp32, then
// rounded to bf16 pair with a single cvt.rn.bf16x2.f32.
__device__ __forceinline__ void split2(float f0, float f1,
                                       uint32_t& hp, uint32_t& lp) {
    const uint32_t u0 = __float_as_uint(f0);
    const uint32_t u1 = __float_as_uint(f1);
    asm("prmt.b32 %0, %1, %2, 0x7632;" : "=r"(hp) : "r"(u0), "r"(u1));
    const float lo0 = f0 - __uint_as_float(u0 & 0xFFFF0000u);
    const float lo1 = f1 - __uint_as_float(u1 & 0xFFFF0000u);
    asm("cvt.rn.bf16x2.f32 %0, %1, %2;" : "=r"(lp) : "f"(lo1), "f"(lo0));
}
__device__ __forceinline__ void split8(const float* f, uint4& hv, uint4& lv) {
    split2(f[0], f[1], hv.x, lv.x);
    split2(f[2], f[3], hv.y, lv.y);
    split2(f[4], f[5], hv.z, lv.z);
    split2(f[6], f[7], hv.w, lv.w);
}

// ============================================================================
// conv_all: one launch for both conversions.
//  blocks [0, A_BLOCKS):       A rows fp32 -> gAhi/gAlo (16 elems/thread)
//  blocks [A_BLOCKS, +B_BLOCKS): W [K,N] -> gBhi/gBlo [N,K] via 64x64 transpose
// ============================================================================
__global__ __launch_bounds__(256) void conv_all(const float* __restrict__ xs,
                                                const float* __restrict__ xq,
                                                const float* __restrict__ W) {
    __shared__ float ts[64][65];
    const int t = threadIdx.x;
    int bid = blockIdx.x;

    if (bid < A_BLOCKS) {
        // ---- A conversion: 4096 elems per block, 16 per thread (one row)
        const size_t e = ((size_t)bid * 256 + t) * 16;
        const int row = (int)(e / IN_DIM);
        const int col = (int)(e % IN_DIM);
        float f[16];
        const float* src = 0;
        if (row < NSHOT)      src = xs + (size_t)row * IN_DIM + col;
        else if (row < MROWS) src = xq + (size_t)(row - NSHOT) * IN_DIM + col;
        if (src) {
#pragma unroll
            for (int i = 0; i < 4; i++)
                *(float4*)&f[i * 4] = *(const float4*)(src + i * 4);
        } else {
#pragma unroll
            for (int i = 0; i < 16; i++) f[i] = 0.f;
        }
        uint4 hv0, lv0, hv1, lv1;
        split8(f,     hv0, lv0);
        split8(f + 8, hv1, lv1);
        *(uint4*)&gAhi[e]     = hv0;
        *(uint4*)&gAhi[e + 8] = hv1;
        *(uint4*)&gAlo[e]     = lv0;
        *(uint4*)&gAlo[e + 8] = lv1;
        return;
    }

    // ---- B transpose + conversion: 64x64 fp32 tile
    bid -= A_BLOCKS;
    const int k0 = (bid % B_KT) * 64;
    const int n0 = (bid / B_KT) * 64;

    // load 64 rows x 64 cols (each thread 4 float4s)
#pragma unroll
    for (int i = 0; i < 4; i++) {
        const int r = i * 16 + (t >> 4);
        const int c = (t & 15) * 4;
        const float4 v = *(const float4*)(W + (size_t)(k0 + r) * NDIM + n0 + c);
        ts[r][c] = v.x; ts[r][c+1] = v.y; ts[r][c+2] = v.z; ts[r][c+3] = v.w;
    }
    __syncthreads();

    // store transposed: thread -> n row t>>2, k chunk (t&3)*16
    const int n  = t >> 2;
    const int kc = (t & 3) * 16;
    float f[16];
#pragma unroll
    for (int j = 0; j < 16; j++) f[j] = ts[kc + j][n];
    uint4 hv0, lv0, hv1, lv1;
    split8(f,     hv0, lv0);
    split8(f + 8, hv1, lv1);
    const size_t o = (size_t)(n0 + n) * IN_DIM + k0 + kc;
    *(uint4*)&gBhi[o]     = hv0;
    *(uint4*)&gBhi[o + 8] = hv1;
    *(uint4*)&gBlo[o]     = lv0;
    *(uint4*)&gBlo[o + 8] = lv1;
}

// ============================================================================
// noop: launch-order shims so gemm_hmma is launch #4 (the one ncu captures)
// ============================================================================
__global__ void noop_kernel() {}

// ============================================================================
// HMMA GEMM (R3-proven per-CTA config): g_part[sp] = A_ph @ B_ph^T, k slice.
// grid (4 N-tiles, 4 M-tiles, 27 splits) = 432 CTAs ~= 3 CTAs/SM.
// 256 threads, 8 warps (4M x 2N). 4-stage cp.async pipeline, wait<=2.
// ============================================================================
__global__ __launch_bounds__(256, 3) void gemm_hmma() {
    extern __shared__ char smem[];
    const uint32_t sbase = smem_u32(smem);
    const int t = threadIdx.x;
    const int wid = t >> 5, lane = t & 31;

    const int n0 = blockIdx.x * BN;
    const int m0 = blockIdx.y * BM;
    const int sp = blockIdx.z;
    const int phase = sp / SUBSPLITS;            // 0: hi*hi  1: hi*lo  2: lo*hi
    const int sub   = sp % SUBSPLITS;
    const int kt0 = sub * KTS_BASE + (sub < KTS_REM ? sub : KTS_REM);
    const int NT  = KTS_BASE + (sub < KTS_REM ? 1 : 0);
    const size_t ksub = (size_t)kt0 * BK;

    const __nv_bfloat16* __restrict__ A = (phase == 2) ? gAlo : gAhi;
    const __nv_bfloat16* __restrict__ B = (phase == 1) ? gBlo : gBhi;

    // ---- loader mapping: thread loads 2 A chunks + 2 B chunks of 16B per stage
    const int lr = t >> 2;          // tile row 0..63
    const int lc = t & 3;           // 16B chunk 0..3
    const uint32_t dA1 = toff(lr, lc),        dA2 = toff(lr + 64, lc);
    const uint32_t dB1 = toff(lr, lc) + 8192, dB2 = toff(lr + 64, lc) + 8192;
    const __nv_bfloat16* pA1 = A + (size_t)(m0 + lr) * IN_DIM + ksub + lc * 8;
    const __nv_bfloat16* pA2 = pA1 + (size_t)64 * IN_DIM;
    const __nv_bfloat16* pB1 = B + (size_t)(n0 + lr) * IN_DIM + ksub + lc * 8;
    const __nv_bfloat16* pB2 = pB1 + (size_t)64 * IN_DIM;

#define LOAD_STAGE(s, kt) do {                                        \
        const uint32_t sb_ = sbase + (s) * STG_BYTES;                  \
        const size_t ko_ = (size_t)(kt) * BK;                          \
        cp16(sb_ + dA1, pA1 + ko_); cp16(sb_ + dA2, pA2 + ko_);        \
        cp16(sb_ + dB1, pB1 + ko_); cp16(sb_ + dB2, pB2 + ko_);        \
    } while (0)

    // ---- compute mapping: warp (wm, wn) owns 32x64 of C
    const int wm = wid >> 1, wn = wid & 1;
    const int fr = lane & 15, fc = lane >> 4;
    uint32_t aoff[2][2], boff[4][2];
#pragma unroll
    for (int mh = 0; mh < 2; mh++)
#pragma unroll
        for (int ks = 0; ks < 2; ks++)
            aoff[mh][ks] = toff(wm * 32 + mh * 16 + fr, ks * 2 + fc);
#pragma unroll
    for (int p = 0; p < 4; p++)
#pragma unroll
        for (int ks = 0; ks < 2; ks++)
            boff[p][ks] = 8192 + toff(wn * 64 + p * 16 + fr, ks * 2 + fc);

    float c[2][8][4];
#pragma unroll
    for (int i = 0; i < 2; i++)
#pragma unroll
        for (int j = 0; j < 8; j++)
#pragma unroll
            for (int k = 0; k < 4; k++) c[i][j][k] = 0.f;

    // ---- prologue: fill stages 0..2
#pragma unroll
    for (int s = 0; s < STAGES - 1; s++) {
        LOAD_STAGE(s, s);
        CP_COMMIT();
    }

    // ---- main loop
    for (int kt = 0; kt < NT; ++kt) {
        CP_WAIT2();
        __syncthreads();

        if (kt + STAGES - 1 < NT)
            LOAD_STAGE((kt + STAGES - 1) & (STAGES - 1), kt + STAGES - 1);
        CP_COMMIT();

        const uint32_t sb = sbase + (kt & (STAGES - 1)) * STG_BYTES;
#pragma unroll
        for (int ks = 0; ks < 2; ks++) {
            uint32_t a0[4], a1[4];
            ldsm4(a0[0], a0[1], a0[2], a0[3], sb + aoff[0][ks]);
            ldsm4(a1[0], a1[1], a1[2], a1[3], sb + aoff[1][ks]);
#pragma unroll
            for (int p = 0; p < 4; p++) {
                uint32_t r0, r1, r2, r3;
                ldsm4(r0, r1, r2, r3, sb + boff[p][ks]);
                uint32_t b0[2] = { r0, r2 };
                uint32_t b1[2] = { r1, r3 };
                mma16816(c[0][2*p],     a0, b0);
                mma16816(c[1][2*p],     a1, b0);
                mma16816(c[0][2*p + 1], a0, b1);
                mma16816(c[1][2*p + 1], a1, b1);
            }
        }
    }

    // ---- epilogue: direct fp32 stores of partials
    float* base = g_part + (size_t)sp * MPAD * NDIM;
    const int row0 = m0 + wm * 32 + (lane >> 2);
    const int col0 = n0 + wn * 64 + (lane & 3) * 2;
#pragma unroll
    for (int mi = 0; mi < 2; mi++)
#pragma unroll
        for (int j = 0; j < 8; j++) {
            const int r = row0 + mi * 16;
            const int cc = col0 + j * 8;
            *(float2*)&base[(size_t)r * NDIM + cc]       = make_float2(c[mi][j][0], c[mi][j][1]);
            *(float2*)&base[(size_t)(r + 8) * NDIM + cc] = make_float2(c[mi][j][2], c[mi][j][3]);
        }
}

// ============================================================================
// split-K reduce + bias (deterministic order, float4-vectorized)
// ============================================================================
__global__ void reduce_bias(const float* __restrict__ bias) {
    const int i4 = blockIdx.x * blockDim.x + threadIdx.x;
    const int e = i4 * 4;
    if (e >= MROWS * NDIM) return;
    const int n = e & (NDIM - 1);
    float4 s = make_float4(0.f, 0.f, 0.f, 0.f);
#pragma unroll
    for (int p = 0; p < TOTSPLITS; p++) {
        const float4 v = *(const float4*)&g_part[(size_t)p * MPAD * NDIM + e];
        s.x += v.x; s.y += v.y; s.z += v.z; s.w += v.w;
    }
    const float4 b = *(const float4*)&bias[n];
    s.x += b.x; s.y += b.y; s.z += b.z; s.w += b.w;
    *(float4*)&g_ze[e] = s;
}

// ============================================================================
// nearest codebook: argmax_k (z.c_k - 0.5||c_k||^2), tie -> min k
// ============================================================================
__global__ __launch_bounds__(512) void nearest_kernel(const float* __restrict__ cb) {
    __shared__ float zs[8][NDIM];
    __shared__ float red[512];
    __shared__ int   redi[512];
    const int t = threadIdx.x;
    const int r0 = blockIdx.x * 8;
#pragma unroll
    for (int g = 0; g < 8; g++) zs[g][t] = g_ze[(r0 + g) * NDIM + t];
    __syncthreads();
    float s[8];
#pragma unroll
    for (int g = 0; g < 8; g++) s[g] = 0.f;
    float cn = 0.f;
#pragma unroll 4
    for (int d = 0; d < NDIM; d++) {
        const float c = cb[d * NK + t];
        cn = fmaf(c, c, cn);
#pragma unroll
        for (int g = 0; g < 8; g++) s[g] = fmaf(zs[g][d], c, s[g]);
    }
    for (int g = 0; g < 8; g++) {
        red[t] = s[g] - 0.5f * cn;
        redi[t] = t;
        __syncthreads();
        for (int off = 256; off > 0; off >>= 1) {
            if (t < off) {
                const float o = red[t + off];
                const int oi = redi[t + off];
                if (o > red[t] || (o == red[t] && oi < redi[t])) { red[t] = o; redi[t] = oi; }
            }
            __syncthreads();
        }
        if (t == 0) g_idx[r0 + g] = redi[0];
        __syncthreads();
    }
}

// ============================================================================
// prototypes: mean of 5 quantized shots, L2-normalized
// ============================================================================
__global__ __launch_bounds__(512) void proto_kernel(const float* __restrict__ cb) {
    const int bw = blockIdx.x, t = threadIdx.x;
    float p = 0.f;
#pragma unroll
    for (int s = 0; s < 5; s++) p += cb[(size_t)t * NK + g_idx[bw * 5 + s]];
    p *= 0.2f;
    __shared__ float red[512];
    red[t] = p * p;
    __syncthreads();
    for (int off = 256; off > 0; off >>= 1) {
        if (t < off) red[t] += red[t + off];
        __syncthreads();
    }
    g_proto[bw * NDIM + t] = p * rsqrtf(red[0]);
}

// ============================================================================
// logits
// ============================================================================
__global__ __launch_bounds__(512) void logits_kernel(
    const float* __restrict__ cb, const float* __restrict__ tptr,
    float* __restrict__ out) {
    const int bq = blockIdx.x, t = threadIdx.x;
    const int b = bq / 75;
    const float v = cb[(size_t)t * NK + g_idx[NSHOT + bq]];
    __shared__ float red[512];
    red[t] = v * v;
    __syncthreads();
    for (int off = 256; off > 0; off >>= 1) {
        if (t < off) red[t] += red[t + off];
        __syncthreads();
    }
    const float vn = v * rsqrtf(red[0]);
    const float temp = *tptr;
    for (int w = 0; w < 5; w++) {
        __syncthreads();
        red[t] = vn * g_proto[(b * 5 + w) * NDIM + t];
        __syncthreads();
        for (int off = 256; off > 0; off >>= 1) {
            if (t < off) red[t] += red[t + off];
            __syncthreads();
        }
        if (t == 0) out[bq * 5 + w] = red[0] * temp;
    }
}

// ============================================================================
extern "C" void kernel_launch(void* const* d_in, const int* in_sizes, int n_in,
                              void* d_out, int out_size) {
    const float* xs   = (const float*)d_in[0];
    const float* xq   = (const float*)d_in[1];
    const float* W    = (const float*)d_in[2];
    const float* bias = (const float*)d_in[3];
    const float* cb   = (const float*)d_in[4];
    const float* temp = (const float*)d_in[5];
    float* out = (float*)d_out;

    cudaFuncSetAttribute(gemm_hmma, cudaFuncAttributeMaxDynamicSharedMemorySize,
                         SMEM_GEMM);

    conv_all<<<A_BLOCKS + B_BLOCKS, 256>>>(xs, xq, W);
    noop_kernel<<<1, 32>>>();   // shims: keep gemm_hmma at launch #4 for ncu
    noop_kernel<<<1, 32>>>();
    gemm_hmma<<<dim3(NDIM / BN, MPAD / BM, TOTSPLITS), 256, SMEM_GEMM>>>();
    reduce_bias<<<(MROWS * NDIM / 4 + 255) / 256, 256>>>(bias);
    nearest_kernel<<<MROWS / 8, 512>>>(cb);
    proto_kernel<<<20, 512>>>(cb);
    logits_kernel<<<300, 512>>>(cb, temp, out);
}

// round 9
// speedup vs baseline: 1.6676x; 1.6676x over previous
#include <cuda_runtime.h>
#include <cuda_bf16.h>
#include <cstdint>

// ============================================================================
// VQMetaBaseline via mma.sync bf16 (compute_103-safe):
// z_e = X @ W + b with truncation-based bf16 hi/lo split (hi = exact top 16
// bits, lo = exact residual rounded to bf16), 3 exact-product passes
// (hi*hi + hi*lo + lo*hi) as grid-z phases, fp32 accumulate ->
// argmin-index parity with fp32 reference. Then nearest/proto/logits.
// GEMM config: R3/R7-proven (256 thr, occ 2, 4 stages, 18 splits).
// ============================================================================

#define IN_DIM 49152
#define NDIM   512
#define NK     512
#define MROWS  400
#define MPAD   512
#define NSHOT  100

// GEMM tiling (R3/R7-proven config)
#define BM 128
#define BN 128
#define BK 32
#define STAGES 4
#define STG_BYTES 16384            // A 8KB + B 8KB per stage
#define SMEM_GEMM (STAGES * STG_BYTES)   // 64 KB -> 2 CTAs/SM

// split-K: 3 phases (hihi, hilo, lohi) x 6 sub-splits
#define SUBSPLITS 6
#define TOTSPLITS 18
#define KSPLIT (IN_DIM / SUBSPLITS)      // 8192
#define NT (KSPLIT / BK)                 // 256 k-tiles per CTA

// conv_all work partition
#define A_BLOCKS ((int)((size_t)MPAD * IN_DIM / (256 * 16)))  // 6144
#define B_KT     (IN_DIM / 64)                                // 768
#define B_BLOCKS (B_KT * (NDIM / 64))                         // 6144

// ---- scratch (static device globals; no runtime allocation) ----------------
__device__ __align__(128) __nv_bfloat16 gAhi[(size_t)MPAD * IN_DIM];
__device__ __align__(128) __nv_bfloat16 gAlo[(size_t)MPAD * IN_DIM];
__device__ __align__(128) __nv_bfloat16 gBhi[(size_t)NDIM * IN_DIM];
__device__ __align__(128) __nv_bfloat16 gBlo[(size_t)NDIM * IN_DIM];
__device__ float g_part[(size_t)TOTSPLITS * MPAD * NDIM];
__device__ float g_ze[MROWS * NDIM];
__device__ int   g_idx[MROWS];
__device__ float g_proto[20 * NDIM];

// ---- helpers ----------------------------------------------------------------
__device__ __forceinline__ uint32_t smem_u32(const void* p) {
    uint32_t a;
    asm("{ .reg .u64 t; cvta.to.shared.u64 t, %1; cvt.u32.u64 %0, t; }"
        : "=r"(a) : "l"(p));
    return a;
}
__device__ __forceinline__ void cp16(uint32_t dst, const void* src) {
    asm volatile("cp.async.cg.shared.global [%0], [%1], 16;"
                 :: "r"(dst), "l"(src) : "memory");
}
#define CP_COMMIT() asm volatile("cp.async.commit_group;" ::: "memory")
#define CP_WAIT2()  asm volatile("cp.async.wait_group 2;" ::: "memory")

__device__ __forceinline__ void ldsm4(uint32_t& r0, uint32_t& r1,
                                      uint32_t& r2, uint32_t& r3, uint32_t a) {
    asm volatile("ldmatrix.sync.aligned.m8n8.x4.shared.b16 {%0,%1,%2,%3}, [%4];"
                 : "=r"(r0), "=r"(r1), "=r"(r2), "=r"(r3) : "r"(a));
}
__device__ __forceinline__ void mma16816(float* c, const uint32_t* a,
                                         const uint32_t* b) {
    asm volatile(
        "mma.sync.aligned.m16n8k16.row.col.f32.bf16.bf16.f32 "
        "{%0,%1,%2,%3},{%4,%5,%6,%7},{%8,%9},{%0,%1,%2,%3};"
        : "+f"(c[0]), "+f"(c[1]), "+f"(c[2]), "+f"(c[3])
        : "r"(a[0]), "r"(a[1]), "r"(a[2]), "r"(a[3]), "r"(b[0]), "r"(b[1]));
}

// smem tile offset: 128 rows x 64B (32 bf16), XOR swizzle -> conflict-free
__device__ __forceinline__ uint32_t toff(int r, int c) {
    return (uint32_t)(r * 64 + ((c ^ ((r >> 1) & 3)) << 4));
}

// ---- fast truncation split: 2 floats -> 1 u32 hi-pair + 1 u32 lo-pair ------
__device__ __forceinline__ void split2(float f0, float f1,
                                       uint32_t& hp, uint32_t& lp) {
    const uint32_t u0 = __float_as_uint(f0);
    const uint32_t u1 = __float_as_uint(f1);
    asm("prmt.b32 %0, %1, %2, 0x7632;" : "=r"(hp) : "r"(u0), "r"(u1));
    const float lo0 = f0 - __uint_as_float(u0 & 0xFFFF0000u);
    const float lo1 = f1 - __uint_as_float(u1 & 0xFFFF0000u);
    asm("cvt.rn.bf16x2.f32 %0, %1, %2;" : "=r"(lp) : "f"(lo1), "f"(lo0));
}
__device__ __forceinline__ void split8(const float* f, uint4& hv, uint4& lv) {
    split2(f[0], f[1], hv.x, lv.x);
    split2(f[2], f[3], hv.y, lv.y);
    split2(f[4], f[5], hv.z, lv.z);
    split2(f[6], f[7], hv.w, lv.w);
}

// ============================================================================
// conv_all: one launch for both conversions.
//  blocks [0, A_BLOCKS):        A rows fp32 -> gAhi/gAlo (16 elems/thread)
//  blocks [A_BLOCKS, +B_BLOCKS): W [K,N] -> gBhi/gBlo [N,K] via 64x64 transpose
// ============================================================================
__global__ __launch_bounds__(256) void conv_all(const float* __restrict__ xs,
                                                const float* __restrict__ xq,
                                                const float* __restrict__ W) {
    __shared__ float ts[64][65];
    const int t = threadIdx.x;
    int bid = blockIdx.x;

    if (bid < A_BLOCKS) {
        const size_t e = ((size_t)bid * 256 + t) * 16;
        const int row = (int)(e / IN_DIM);
        const int col = (int)(e % IN_DIM);
        float f[16];
        const float* src = 0;
        if (row < NSHOT)      src = xs + (size_t)row * IN_DIM + col;
        else if (row < MROWS) src = xq + (size_t)(row - NSHOT) * IN_DIM + col;
        if (src) {
#pragma unroll
            for (int i = 0; i < 4; i++)
                *(float4*)&f[i * 4] = *(const float4*)(src + i * 4);
        } else {
#pragma unroll
            for (int i = 0; i < 16; i++) f[i] = 0.f;
        }
        uint4 hv0, lv0, hv1, lv1;
        split8(f,     hv0, lv0);
        split8(f + 8, hv1, lv1);
        *(uint4*)&gAhi[e]     = hv0;
        *(uint4*)&gAhi[e + 8] = hv1;
        *(uint4*)&gAlo[e]     = lv0;
        *(uint4*)&gAlo[e + 8] = lv1;
        return;
    }

    // ---- B transpose + conversion: 64x64 fp32 tile
    bid -= A_BLOCKS;
    const int k0 = (bid % B_KT) * 64;
    const int n0 = (bid / B_KT) * 64;

#pragma unroll
    for (int i = 0; i < 4; i++) {
        const int r = i * 16 + (t >> 4);
        const int c = (t & 15) * 4;
        const float4 v = *(const float4*)(W + (size_t)(k0 + r) * NDIM + n0 + c);
        ts[r][c] = v.x; ts[r][c+1] = v.y; ts[r][c+2] = v.z; ts[r][c+3] = v.w;
    }
    __syncthreads();

    const int n  = t >> 2;
    const int kc = (t & 3) * 16;
    float f[16];
#pragma unroll
    for (int j = 0; j < 16; j++) f[j] = ts[kc + j][n];
    uint4 hv0, lv0, hv1, lv1;
    split8(f,     hv0, lv0);
    split8(f + 8, hv1, lv1);
    const size_t o = (size_t)(n0 + n) * IN_DIM + k0 + kc;
    *(uint4*)&gBhi[o]     = hv0;
    *(uint4*)&gBhi[o + 8] = hv1;
    *(uint4*)&gBlo[o]     = lv0;
    *(uint4*)&gBlo[o + 8] = lv1;
}

// ============================================================================
// noop: launch-order shims so conv_all is launch #4 (the one ncu captures)
// ============================================================================
__global__ void noop_kernel() {}

// ============================================================================
// HMMA GEMM (R3/R7-proven): g_part[sp] = A_ph @ B_ph^T over k slice
// grid (4 N-tiles, 4 M-tiles, 18 splits), 256 threads, 8 warps (4M x 2N).
// 4-stage cp.async pipeline, wait<=2, occ 2.
// ============================================================================
__global__ __launch_bounds__(256, 2) void gemm_hmma() {
    extern __shared__ char smem[];
    const uint32_t sbase = smem_u32(smem);
    const int t = threadIdx.x;
    const int wid = t >> 5, lane = t & 31;

    const int n0 = blockIdx.x * BN;
    const int m0 = blockIdx.y * BM;
    const int sp = blockIdx.z;
    const int phase = sp / SUBSPLITS;            // 0: hi*hi  1: hi*lo  2: lo*hi
    const size_t ksub = (size_t)(sp % SUBSPLITS) * KSPLIT;

    const __nv_bfloat16* __restrict__ A = (phase == 2) ? gAlo : gAhi;
    const __nv_bfloat16* __restrict__ B = (phase == 1) ? gBlo : gBhi;

    const int lr = t >> 2;          // tile row 0..63
    const int lc = t & 3;           // 16B chunk 0..3
    const uint32_t dA1 = toff(lr, lc),        dA2 = toff(lr + 64, lc);
    const uint32_t dB1 = toff(lr, lc) + 8192, dB2 = toff(lr + 64, lc) + 8192;
    const __nv_bfloat16* pA1 = A + (size_t)(m0 + lr) * IN_DIM + ksub + lc * 8;
    const __nv_bfloat16* pA2 = pA1 + (size_t)64 * IN_DIM;
    const __nv_bfloat16* pB1 = B + (size_t)(n0 + lr) * IN_DIM + ksub + lc * 8;
    const __nv_bfloat16* pB2 = pB1 + (size_t)64 * IN_DIM;

#define LOAD_STAGE(s, kt) do {                                        \
        const uint32_t sb_ = sbase + (s) * STG_BYTES;                  \
        const size_t ko_ = (size_t)(kt) * BK;                          \
        cp16(sb_ + dA1, pA1 + ko_); cp16(sb_ + dA2, pA2 + ko_);        \
        cp16(sb_ + dB1, pB1 + ko_); cp16(sb_ + dB2, pB2 + ko_);        \
    } while (0)

    const int wm = wid >> 1, wn = wid & 1;
    const int fr = lane & 15, fc = lane >> 4;
    uint32_t aoff[2][2], boff[4][2];
#pragma unroll
    for (int mh = 0; mh < 2; mh++)
#pragma unroll
        for (int ks = 0; ks < 2; ks++)
            aoff[mh][ks] = toff(wm * 32 + mh * 16 + fr, ks * 2 + fc);
#pragma unroll
    for (int p = 0; p < 4; p++)
#pragma unroll
        for (int ks = 0; ks < 2; ks++)
            boff[p][ks] = 8192 + toff(wn * 64 + p * 16 + fr, ks * 2 + fc);

    float c[2][8][4];
#pragma unroll
    for (int i = 0; i < 2; i++)
#pragma unroll
        for (int j = 0; j < 8; j++)
#pragma unroll
            for (int k = 0; k < 4; k++) c[i][j][k] = 0.f;

#pragma unroll
    for (int s = 0; s < STAGES - 1; s++) {
        LOAD_STAGE(s, s);
        CP_COMMIT();
    }

    for (int kt = 0; kt < NT; ++kt) {
        CP_WAIT2();
        __syncthreads();

        if (kt + STAGES - 1 < NT)
            LOAD_STAGE((kt + STAGES - 1) & (STAGES - 1), kt + STAGES - 1);
        CP_COMMIT();

        const uint32_t sb = sbase + (kt & (STAGES - 1)) * STG_BYTES;
#pragma unroll
        for (int ks = 0; ks < 2; ks++) {
            uint32_t a0[4], a1[4];
            ldsm4(a0[0], a0[1], a0[2], a0[3], sb + aoff[0][ks]);
            ldsm4(a1[0], a1[1], a1[2], a1[3], sb + aoff[1][ks]);
#pragma unroll
            for (int p = 0; p < 4; p++) {
                uint32_t r0, r1, r2, r3;
                ldsm4(r0, r1, r2, r3, sb + boff[p][ks]);
                uint32_t b0[2] = { r0, r2 };
                uint32_t b1[2] = { r1, r3 };
                mma16816(c[0][2*p],     a0, b0);
                mma16816(c[1][2*p],     a1, b0);
                mma16816(c[0][2*p + 1], a0, b1);
                mma16816(c[1][2*p + 1], a1, b1);
            }
        }
    }

    float* base = g_part + (size_t)sp * MPAD * NDIM;
    const int row0 = m0 + wm * 32 + (lane >> 2);
    const int col0 = n0 + wn * 64 + (lane & 3) * 2;
#pragma unroll
    for (int mi = 0; mi < 2; mi++)
#pragma unroll
        for (int j = 0; j < 8; j++) {
            const int r = row0 + mi * 16;
            const int cc = col0 + j * 8;
            *(float2*)&base[(size_t)r * NDIM + cc]       = make_float2(c[mi][j][0], c[mi][j][1]);
            *(float2*)&base[(size_t)(r + 8) * NDIM + cc] = make_float2(c[mi][j][2], c[mi][j][3]);
        }
}

// ============================================================================
// split-K reduce + bias (deterministic order, float4-vectorized)
// ============================================================================
__global__ void reduce_bias(const float* __restrict__ bias) {
    const int i4 = blockIdx.x * blockDim.x + threadIdx.x;
    const int e = i4 * 4;
    if (e >= MROWS * NDIM) return;
    const int n = e & (NDIM - 1);
    float4 s = make_float4(0.f, 0.f, 0.f, 0.f);
#pragma unroll
    for (int p = 0; p < TOTSPLITS; p++) {
        const float4 v = *(const float4*)&g_part[(size_t)p * MPAD * NDIM + e];
        s.x += v.x; s.y += v.y; s.z += v.z; s.w += v.w;
    }
    const float4 b = *(const float4*)&bias[n];
    s.x += b.x; s.y += b.y; s.z += b.z; s.w += b.w;
    *(float4*)&g_ze[e] = s;
}

// ============================================================================
// nearest codebook: argmax_k (z.c_k - 0.5||c_k||^2), tie -> min k
// ============================================================================
__global__ __launch_bounds__(512) void nearest_kernel(const float* __restrict__ cb) {
    __shared__ float zs[8][NDIM];
    __shared__ float red[512];
    __shared__ int   redi[512];
    const int t = threadIdx.x;
    const int r0 = blockIdx.x * 8;
#pragma unroll
    for (int g = 0; g < 8; g++) zs[g][t] = g_ze[(r0 + g) * NDIM + t];
    __syncthreads();
    float s[8];
#pragma unroll
    for (int g = 0; g < 8; g++) s[g] = 0.f;
    float cn = 0.f;
#pragma unroll 4
    for (int d = 0; d < NDIM; d++) {
        const float c = cb[d * NK + t];
        cn = fmaf(c, c, cn);
#pragma unroll
        for (int g = 0; g < 8; g++) s[g] = fmaf(zs[g][d], c, s[g]);
    }
    for (int g = 0; g < 8; g++) {
        red[t] = s[g] - 0.5f * cn;
        redi[t] = t;
        __syncthreads();
        for (int off = 256; off > 0; off >>= 1) {
            if (t < off) {
                const float o = red[t + off];
                const int oi = redi[t + off];
                if (o > red[t] || (o == red[t] && oi < redi[t])) { red[t] = o; redi[t] = oi; }
            }
            __syncthreads();
        }
        if (t == 0) g_idx[r0 + g] = redi[0];
        __syncthreads();
    }
}

// ============================================================================
// prototypes: mean of 5 quantized shots, L2-normalized
// ============================================================================
__global__ __launch_bounds__(512) void proto_kernel(const float* __restrict__ cb) {
    const int bw = blockIdx.x, t = threadIdx.x;
    float p = 0.f;
#pragma unroll
    for (int s = 0; s < 5; s++) p += cb[(size_t)t * NK + g_idx[bw * 5 + s]];
    p *= 0.2f;
    __shared__ float red[512];
    red[t] = p * p;
    __syncthreads();
    for (int off = 256; off > 0; off >>= 1) {
        if (t < off) red[t] += red[t + off];
        __syncthreads();
    }
    g_proto[bw * NDIM + t] = p * rsqrtf(red[0]);
}

// ============================================================================
// logits
// ============================================================================
__global__ __launch_bounds__(512) void logits_kernel(
    const float* __restrict__ cb, const float* __restrict__ tptr,
    float* __restrict__ out) {
    const int bq = blockIdx.x, t = threadIdx.x;
    const int b = bq / 75;
    const float v = cb[(size_t)t * NK + g_idx[NSHOT + bq]];
    __shared__ float red[512];
    red[t] = v * v;
    __syncthreads();
    for (int off = 256; off > 0; off >>= 1) {
        if (t < off) red[t] += red[t + off];
        __syncthreads();
    }
    const float vn = v * rsqrtf(red[0]);
    const float temp = *tptr;
    for (int w = 0; w < 5; w++) {
        __syncthreads();
        red[t] = vn * g_proto[(b * 5 + w) * NDIM + t];
        __syncthreads();
        for (int off = 256; off > 0; off >>= 1) {
            if (t < off) red[t] += red[t + off];
            __syncthreads();
        }
        if (t == 0) out[bq * 5 + w] = red[0] * temp;
    }
}

// ============================================================================
extern "C" void kernel_launch(void* const* d_in, const int* in_sizes, int n_in,
                              void* d_out, int out_size) {
    const float* xs   = (const float*)d_in[0];
    const float* xq   = (const float*)d_in[1];
    const float* W    = (const float*)d_in[2];
    const float* bias = (const float*)d_in[3];
    const float* cb   = (const float*)d_in[4];
    const float* temp = (const float*)d_in[5];
    float* out = (float*)d_out;

    cudaFuncSetAttribute(gemm_hmma, cudaFuncAttributeMaxDynamicSharedMemorySize,
                         SMEM_GEMM);

    noop_kernel<<<1, 32>>>();   // shims: make conv_all launch #4 (ncu target)
    noop_kernel<<<1, 32>>>();
    noop_kernel<<<1, 32>>>();
    conv_all<<<A_BLOCKS + B_BLOCKS, 256>>>(xs, xq, W);
    gemm_hmma<<<dim3(NDIM / BN, MPAD / BM, TOTSPLITS), 256, SMEM_GEMM>>>();
    reduce_bias<<<(MROWS * NDIM / 4 + 255) / 256, 256>>>(bias);
    nearest_kernel<<<MROWS / 8, 512>>>(cb);
    proto_kernel<<<20, 512>>>(cb);
    logits_kernel<<<300, 512>>>(cb, temp, out);
}